// round 17
// baseline (speedup 1.0000x reference)
#include <cuda_runtime.h>
#include <cstdint>
#include <cstddef>

// ---------------- problem constants ----------------
#define NN   100000            // nodes
#define NE   1600000           // original edges (self-loops handled explicitly)

// ---------------- device scratch (no allocations allowed) ----------------
__device__            int      g_cnt[NN];        // in-degree (zeroed by last kernel)
__device__            int      g_rowptr[NN];     // CSR row starts
__device__            int      g_pos[NN];        // scatter cursors
__device__            int      g_esrc[NE];       // src ids grouped by dst
__device__ __align__(16) float g_eas[(size_t)NE * 16];  // edge attrs, CSR order
__device__ __align__(16) float g_xl[NN * 64];
__device__ __align__(16) float g_xr[NN * 64];
__device__ __align__(16) float g_h[NN * 64];

// ---------------- CSR build ----------------
__global__ void k_hist(const int* __restrict__ ei) {
    int e = blockIdx.x * blockDim.x + threadIdx.x;
    if (e >= NE) return;
    atomicAdd(&g_cnt[ei[NE + e]], 1);
}

// single-block exclusive scan over g_cnt -> g_rowptr, g_pos
__global__ void k_scan() {
    __shared__ int ps[1024];
    const int CH = (NN + 1023) / 1024;           // 98
    int t   = threadIdx.x;
    int beg = t * CH;
    int end = beg + CH < NN ? beg + CH : NN;
    int s = 0;
    for (int i = beg; i < end; i++) s += g_cnt[i];
    ps[t] = s;
    __syncthreads();
    for (int off = 1; off < 1024; off <<= 1) {
        int v = (t >= off) ? ps[t - off] : 0;
        __syncthreads();
        ps[t] += v;
        __syncthreads();
    }
    int base = ps[t] - s;                        // exclusive
    for (int i = beg; i < end; i++) {
        g_rowptr[i] = base;
        g_pos[i]    = base;
        base += g_cnt[i];
    }
}

// scatter src ids AND edge attrs into CSR (dst-grouped) order
__global__ void k_scatter(const int* __restrict__ ei, const float* __restrict__ ea) {
    int e = blockIdx.x * blockDim.x + threadIdx.x;
    if (e >= NE) return;
    int src = ei[e];
    int dst = ei[NE + e];
    int idx = atomicAdd(&g_pos[dst], 1);
    g_esrc[idx] = src;
    const float4* v4 = (const float4*)(ea + (size_t)e * 16);
    float4* o4 = (float4*)(g_eas + (size_t)idx * 16);
    o4[0] = v4[0]; o4[1] = v4[1]; o4[2] = v4[2]; o4[3] = v4[3];
}

// ---------------- GEMM: C[n,64] = A[n,K] @ W[K,64] + bias ----------------
// ASEL: 0 -> external A (x), 1 -> g_h.   CSEL: 0 -> g_xl, 1 -> g_xr.
// 64 rows/block, 256 threads, 8x2 register tile, BK=32. (R4/R6-proven shape)
template <int K, int ASEL, int CSEL>
__global__ void k_gemm64(const float* __restrict__ Aext,
                         const float* __restrict__ W,
                         const float* __restrict__ bias, int nrows) {
    const float* A = (ASEL == 0) ? Aext : (const float*)g_h;
    float*       C = (CSEL == 0) ? g_xl : g_xr;
    __shared__ float As[64 * 33];
    __shared__ float Ws[32 * 64];
    __shared__ float bs[64];
    int tid  = threadIdx.x;
    int row0 = blockIdx.x * 64;
    if (tid < 64) bs[tid] = bias[tid];
    int tc = tid & 31;
    int tr = tid >> 5;
    float acc[8][2];
#pragma unroll
    for (int r = 0; r < 8; r++) { acc[r][0] = 0.f; acc[r][1] = 0.f; }

    for (int k0 = 0; k0 < K; k0 += 32) {
        __syncthreads();
#pragma unroll
        for (int i = 0; i < 8; i++) {
            int lin = tid + i * 256;
            int r = lin >> 5, kk = lin & 31;
            int gr = row0 + r;
            As[r * 33 + kk] = (gr < nrows) ? A[(size_t)gr * K + k0 + kk] : 0.f;
        }
#pragma unroll
        for (int i = 0; i < 8; i++) {
            int lin = tid + i * 256;
            int kk = lin >> 6, j = lin & 63;
            Ws[kk * 64 + j] = W[(size_t)(k0 + kk) * 64 + j];
        }
        __syncthreads();
#pragma unroll
        for (int kk = 0; kk < 32; kk++) {
            float w0 = Ws[kk * 64 + tc];
            float w1 = Ws[kk * 64 + tc + 32];
#pragma unroll
            for (int r = 0; r < 8; r++) {
                float xv = As[(tr * 8 + r) * 33 + kk];
                acc[r][0] = fmaf(xv, w0, acc[r][0]);
                acc[r][1] = fmaf(xv, w1, acc[r][1]);
            }
        }
    }
#pragma unroll
    for (int r = 0; r < 8; r++) {
        int gr = row0 + tr * 8 + r;
        if (gr < nrows) {
            C[(size_t)gr * 64 + tc]      = acc[r][0] + bs[tc];
            C[(size_t)gr * 64 + tc + 32] = acc[r][1] + bs[tc + 32];
        }
    }
}

// ---------------- fused GATv2 layer, warp per destination node -------------
// R6 SHFL body + self-loop ee via linearity (mean of per-edge ee sums).
// HEADS8: 1 -> 8 heads of 8ch, 0 -> 1 head of 64ch.
// OUTMODE: 0 -> g_h with bias+ELU (layer1), 1 -> out with bias (layer2,
// also zeroes g_cnt for the next graph replay).
template <int HEADS8, int OUTMODE>
__global__ void k_node(const float* __restrict__ We,
                       const float* __restrict__ att,
                       const float* __restrict__ bias,
                       float* __restrict__ out) {
    __shared__ float Ws[16 * 64];
    __shared__ float atts[64];
    __shared__ float bs[64];
    int tid = threadIdx.x;
    for (int i = tid; i < 16 * 64; i += 256) Ws[i] = We[i];
    if (tid < 64) { atts[tid] = att[tid]; bs[tid] = bias[tid]; }
    __syncthreads();

    int n = (blockIdx.x * 256 + tid) >> 5;
    if (n >= NN) return;
    int lane = tid & 31;
    int c0 = 2 * lane;

    float2 xr = *(const float2*)(g_xr + (size_t)n * 64 + c0);
    float2 a2 = *(const float2*)&atts[c0];

    float den = 0.f, acc0 = 0.f, acc1 = 0.f;
    float sumE0 = 0.f, sumE1 = 0.f;          // raw ee sums for self-loop mean

    int beg = g_rowptr[n];
    int cnt = g_cnt[n];
    int npair = cnt >> 1;

    // -------- main loop: 2 edges per iteration (R6 SHFL broadcast) --------
    int i = beg;
    for (int p = 0; p < npair; p++, i += 2) {
        int sA = g_esrc[i];
        int sB = g_esrc[i + 1];
        // lanes 0-15: edge i attrs; lanes 16-31: edge i+1 attrs (one 128B load)
        float eav = g_eas[(size_t)i * 16 + lane];
        // issue gathers early; consumed after the shfl loop
        float2 xa = *(const float2*)(g_xl + (size_t)sA * 64 + c0);
        float2 xb = *(const float2*)(g_xl + (size_t)sB * 64 + c0);
        float eA0 = 0.f, eA1 = 0.f, eB0 = 0.f, eB1 = 0.f;
#pragma unroll
        for (int k = 0; k < 16; k++) {
            float a  = __shfl_sync(0xffffffffu, eav, k);
            float b  = __shfl_sync(0xffffffffu, eav, 16 + k);
            float2 w = *(const float2*)&Ws[k * 64 + c0];
            eA0 = fmaf(a, w.x, eA0);
            eA1 = fmaf(a, w.y, eA1);
            eB0 = fmaf(b, w.x, eB0);
            eB1 = fmaf(b, w.y, eB1);
        }
        sumE0 += eA0 + eB0;
        sumE1 += eA1 + eB1;
        float zA0 = xa.x + xr.x + eA0; zA0 = zA0 > 0.f ? zA0 : 0.2f * zA0;
        float zA1 = xa.y + xr.y + eA1; zA1 = zA1 > 0.f ? zA1 : 0.2f * zA1;
        float zB0 = xb.x + xr.x + eB0; zB0 = zB0 > 0.f ? zB0 : 0.2f * zB0;
        float zB1 = xb.y + xr.y + eB1; zB1 = zB1 > 0.f ? zB1 : 0.2f * zB1;
        float pA = fmaf(zA0, a2.x, zA1 * a2.y);
        float pB = fmaf(zB0, a2.x, zB1 * a2.y);
        if (HEADS8) {
            pA += __shfl_xor_sync(0xffffffffu, pA, 1);
            pA += __shfl_xor_sync(0xffffffffu, pA, 2);
            pB += __shfl_xor_sync(0xffffffffu, pB, 1);
            pB += __shfl_xor_sync(0xffffffffu, pB, 2);
        } else {
#pragma unroll
            for (int o = 1; o < 32; o <<= 1) {
                pA += __shfl_xor_sync(0xffffffffu, pA, o);
                pB += __shfl_xor_sync(0xffffffffu, pB, o);
            }
        }
        float ehA = __expf(pA);       // shift-invariant: no max needed
        float ehB = __expf(pB);
        den += ehA + ehB;
        acc0 = fmaf(ehA, xa.x, acc0);
        acc1 = fmaf(ehA, xa.y, acc1);
        acc0 = fmaf(ehB, xb.x, acc0);
        acc1 = fmaf(ehB, xb.y, acc1);
    }

    // -------- odd tail edge --------
    if (cnt & 1) {
        int sA = g_esrc[i];
        float eav = (lane < 16) ? g_eas[(size_t)i * 16 + lane] : 0.f;
        float2 xa = *(const float2*)(g_xl + (size_t)sA * 64 + c0);
        float e0 = 0.f, e1 = 0.f;
#pragma unroll
        for (int k = 0; k < 16; k++) {
            float a  = __shfl_sync(0xffffffffu, eav, k);
            float2 w = *(const float2*)&Ws[k * 64 + c0];
            e0 = fmaf(a, w.x, e0);
            e1 = fmaf(a, w.y, e1);
        }
        sumE0 += e0;
        sumE1 += e1;
        float z0 = xa.x + xr.x + e0; z0 = z0 > 0.f ? z0 : 0.2f * z0;
        float z1 = xa.y + xr.y + e1; z1 = z1 > 0.f ? z1 : 0.2f * z1;
        float p = fmaf(z0, a2.x, z1 * a2.y);
        if (HEADS8) {
            p += __shfl_xor_sync(0xffffffffu, p, 1);
            p += __shfl_xor_sync(0xffffffffu, p, 2);
        } else {
#pragma unroll
            for (int o = 1; o < 32; o <<= 1) p += __shfl_xor_sync(0xffffffffu, p, o);
        }
        float eh = __expf(p);
        den += eh;
        acc0 = fmaf(eh, xa.x, acc0);
        acc1 = fmaf(eh, xa.y, acc1);
    }

    // -------- self loop: ee = mean of per-edge ee (linearity of ea @ We) ----
    {
        float invc = 1.0f / (float)(cnt > 0 ? cnt : 1);
        float e0 = sumE0 * invc;
        float e1 = sumE1 * invc;
        float2 xa = *(const float2*)(g_xl + (size_t)n * 64 + c0);
        float z0 = xa.x + xr.x + e0; z0 = z0 > 0.f ? z0 : 0.2f * z0;
        float z1 = xa.y + xr.y + e1; z1 = z1 > 0.f ? z1 : 0.2f * z1;
        float p = fmaf(z0, a2.x, z1 * a2.y);
        if (HEADS8) {
            p += __shfl_xor_sync(0xffffffffu, p, 1);
            p += __shfl_xor_sync(0xffffffffu, p, 2);
        } else {
#pragma unroll
            for (int o = 1; o < 32; o <<= 1) p += __shfl_xor_sync(0xffffffffu, p, o);
        }
        float eh = __expf(p);
        den += eh;
        acc0 = fmaf(eh, xa.x, acc0);
        acc1 = fmaf(eh, xa.y, acc1);
    }

    float inv = 1.0f / (den + 1e-16f);
    float v0 = acc0 * inv + bs[c0];
    float v1 = acc1 * inv + bs[c0 + 1];
    if (OUTMODE == 0) {
        v0 = v0 > 0.f ? v0 : expm1f(v0);
        v1 = v1 > 0.f ? v1 : expm1f(v1);
        g_h[(size_t)n * 64 + c0]     = v0;
        g_h[(size_t)n * 64 + c0 + 1] = v1;
    } else {
        out[(size_t)n * 64 + c0]     = v0;
        out[(size_t)n * 64 + c0 + 1] = v1;
        if (lane == 0) g_cnt[n] = 0;           // reset for next graph replay
    }
}

// ---------------- launch (kernel launches ONLY) ----------------------------
extern "C" void kernel_launch(void* const* d_in, const int* in_sizes, int n_in,
                              void* d_out, int out_size) {
    (void)in_sizes; (void)n_in; (void)out_size;
    const float* x    = (const float*)d_in[0];
    const int*   ei   = (const int*)d_in[1];     // int32 (JAX x64 disabled)
    const float* ea   = (const float*)d_in[2];
    const float* Wl1  = (const float*)d_in[3];
    const float* bl1  = (const float*)d_in[4];
    const float* Wr1  = (const float*)d_in[5];
    const float* br1  = (const float*)d_in[6];
    const float* We1  = (const float*)d_in[7];
    const float* att1 = (const float*)d_in[8];
    const float* b1   = (const float*)d_in[9];
    const float* Wl2  = (const float*)d_in[10];
    const float* bl2  = (const float*)d_in[11];
    const float* Wr2  = (const float*)d_in[12];
    const float* br2  = (const float*)d_in[13];
    const float* We2  = (const float*)d_in[14];
    const float* att2 = (const float*)d_in[15];
    const float* b2   = (const float*)d_in[16];
    float* out = (float*)d_out;

    const int TB = 256;
    const int node_blocks = (NN * 32 + TB - 1) / TB;   // warp per node

    // CSR build (g_cnt pre-zeroed: static init on first call, last kernel after)
    k_hist<<<(NE + TB - 1) / TB, TB>>>(ei);
    k_scan<<<1, 1024>>>();
    k_scatter<<<(NE + TB - 1) / TB, TB>>>(ei, ea);

    // layer 1: xl = x@Wl1+bl1, xr = x@Wr1+br1 (split GEMMs: higher occupancy)
    k_gemm64<128, 0, 0><<<(NN + 63) / 64, 256>>>(x, Wl1, bl1, NN);
    k_gemm64<128, 0, 1><<<(NN + 63) / 64, 256>>>(x, Wr1, br1, NN);
    k_node<1, 0><<<node_blocks, TB>>>(We1, att1, b1, out);

    // layer 2: from g_h (ASEL=1)
    k_gemm64<64, 1, 0><<<(NN + 63) / 64, 256>>>(nullptr, Wl2, bl2, NN);
    k_gemm64<64, 1, 1><<<(NN + 63) / 64, 256>>>(nullptr, Wr2, br2, NN);
    k_node<0, 1><<<node_blocks, TB>>>(We2, att2, b2, out);
}